// round 16
// baseline (speedup 1.0000x reference)
#include <cuda_runtime.h>
#include <math.h>

// ---------------------------------------------------------------------------
// FusionHead: B=65536, D=192, H=3, HD=64, FP=128
// Round 15: transposed-activation FFMA2 GEMMs.
//  - activations live in smem TRANSPOSED: actT[dim][row], row stride 36
//  - GEMM warps tile 4(M) x 2(N); lanes carry columns (scalar weight LDG.32,
//    packed (w,w)); f32x2 accumulators carry ROW PAIRS loaded as LDS.128
//    broadcasts -> weight wavefronts halved vs col-pair scheme.
//  - 16 batch rows (32 token rows) per block, 256 thr, 83KB smem, 2 blocks/SM.
// ---------------------------------------------------------------------------

#define D_MODEL 192
#define ROWS_PER_BLOCK 16               // batch rows per block
#define TOK_ROWS 32                     // token rows per block
#define NTHREADS 256
#define STRIDE 36                       // smem row stride (floats), 16B-aligned, bank-padded

// scratch offsets (floats)
#define OFF_WPT    0
#define OFF_WTT    36864
#define OFF_INWGT  73728          // [3][192][192] gathered+transposed in-proj
#define OFF_INBG   184320         // [3][192] gathered in-proj bias
#define OFF_OUTWT  184896
#define OFF_FFN1T  221760         // [192][384]
#define OFF_FFN2T  295488         // [384][192]
#define OFF_CLS1T  369216
#define OFF_FPT    406080         // [192][128]
#define SCRATCH_FLOATS 430656

__device__ float g_scratch[SCRATCH_FLOATS];

// ---------------------------------------------------------------------------
// Merged prep kernel (transposes + in-proj gather), grid-stride. (unchanged)
// ---------------------------------------------------------------------------
__global__ void k_prep(const float* __restrict__ Wp, const float* __restrict__ Wt,
                       const float* __restrict__ out_w,
                       const float* __restrict__ ffn_w1, const float* __restrict__ ffn_w2,
                       const float* __restrict__ cls_w1, const float* __restrict__ fp_w,
                       const float* __restrict__ in_w,  const float* __restrict__ in_b) {
    const int t0 = blockIdx.x * blockDim.x + threadIdx.x;
    const int stride = gridDim.x * blockDim.x;
    auto tr = [&](const float* src, int N, int K, int off) {
        for (int i = t0; i < N * K; i += stride) {
            int n = i / K, k = i % K;
            g_scratch[off + k * N + n] = src[i];
        }
    };
    tr(Wp,     192, 192, OFF_WPT);
    tr(Wt,     192, 192, OFF_WTT);
    tr(out_w,  192, 192, OFF_OUTWT);
    tr(ffn_w1, 384, 192, OFF_FFN1T);
    tr(ffn_w2, 192, 384, OFF_FFN2T);
    tr(cls_w1, 192, 192, OFF_CLS1T);
    tr(fp_w,   128, 192, OFF_FPT);
    for (int idx = t0; idx < 3 * 192 * 192; idx += stride) {
        int h   = idx / (192 * 192);
        int rem = idx % (192 * 192);
        int k   = rem / 192;
        int j   = rem % 192;
        int part = j / 64, jj = j % 64;
        int srcrow = part * 192 + h * 64 + jj;
        g_scratch[OFF_INWGT + idx] = in_w[srcrow * 192 + k];
        if (k == 0) g_scratch[OFF_INBG + h * 192 + j] = in_b[srcrow];
    }
}

// ---------------------------------------------------------------------------
// f32x2 helpers
// ---------------------------------------------------------------------------
__device__ __forceinline__ unsigned long long pack2(float lo, float hi) {
    unsigned long long r;
    asm("mov.b64 %0, {%1, %2};" : "=l"(r) : "f"(lo), "f"(hi));
    return r;
}
__device__ __forceinline__ void unpack2(unsigned long long p, float& lo, float& hi) {
    asm("mov.b64 {%0, %1}, %2;" : "=f"(lo), "=f"(hi) : "l"(p));
}
__device__ __forceinline__ unsigned long long ffma2(
    unsigned long long a, unsigned long long b, unsigned long long c) {
    unsigned long long d;
    asm("fma.rn.f32x2 %0, %1, %2, %3;" : "=l"(d) : "l"(a), "l"(b), "l"(c));
    return d;
}

// ---------------------------------------------------------------------------
// Transposed GEMM.
//   actT: [K][STRIDE] smem, logical rows 0..M-1 in the row axis
//   WT:   [K][wN] in g_scratch (row-major over output cols)
//   outT: [colDim][STRIDE] smem, written at rows outRow0 + 0..M-1
// Warps: 4 M-groups (w&3) x 2 N-groups (w>>2). Lane carries NC = N/64 cols.
// Accumulators are f32x2 over ROW PAIRS (RP = M/8 pairs per thread).
// ---------------------------------------------------------------------------
template<int M, int N, int K, bool RELU, bool ADDTO>
__device__ __forceinline__ void gemmT(
    const float* __restrict__ actT,
    const float* __restrict__ WT, int wN,
    const float* __restrict__ bias,
    float* __restrict__ outT, int outRow0, int tid)
{
    static_assert(M % 16 == 0 && N % 64 == 0 && K % 2 == 0, "shape");
    const int lane = tid & 31;
    const int w    = tid >> 5;
    const int mg   = w & 3;          // M group
    const int ng   = w >> 2;         // N group (0..1)
    constexpr int RP = M / 8;        // row pairs per thread
    constexpr int RH = RP / 2;       // ulonglong2 loads per k
    constexpr int NC = N / 64;       // cols per lane

    unsigned long long acc[RP][NC];
    #pragma unroll
    for (int r = 0; r < RP; ++r)
        #pragma unroll
        for (int i = 0; i < NC; ++i) acc[r][i] = 0ull;

    const int rbase = mg * (M / 4);
    const float* aP = actT + rbase;
    const float* wP = WT + ng * (N / 2) + lane;

    ulonglong2 aA[RH], aB[RH];
    float wA[NC], wB[NC];

#define GLOADA(AB, kk)                                                          \
    _Pragma("unroll")                                                           \
    for (int m = 0; m < RH; ++m)                                                \
        AB[m] = *reinterpret_cast<const ulonglong2*>(aP + (kk) * STRIDE + 4 * m);

#define GLOADW(WB, kk)                                                          \
    _Pragma("unroll")                                                           \
    for (int i = 0; i < NC; ++i) WB[i] = wP[(kk) * wN + 32 * i];

#define GSTEP(AB, WB)                                                           \
    _Pragma("unroll")                                                           \
    for (int i = 0; i < NC; ++i) {                                              \
        unsigned long long ww = pack2(WB[i], WB[i]);                            \
        _Pragma("unroll")                                                       \
        for (int m = 0; m < RH; ++m) {                                          \
            acc[2 * m][i]     = ffma2(AB[m].x, ww, acc[2 * m][i]);              \
            acc[2 * m + 1][i] = ffma2(AB[m].y, ww, acc[2 * m + 1][i]);          \
        }                                                                       \
    }

    GLOADA(aA, 0); GLOADW(wA, 0);
    GLOADA(aB, 1); GLOADW(wB, 1);

    #pragma unroll 1
    for (int k = 0; k < K; k += 2) {
        int k2 = (k + 2 < K) ? k + 2 : 0;   // clamped: tail loads are dead
        int k3 = (k + 3 < K) ? k + 3 : 0;
        GSTEP(aA, wA); GLOADA(aA, k2); GLOADW(wA, k2);
        GSTEP(aB, wB); GLOADA(aB, k3); GLOADW(wB, k3);
    }
#undef GLOADA
#undef GLOADW
#undef GSTEP

    #pragma unroll
    for (int r = 0; r < RP; ++r)
        #pragma unroll
        for (int i = 0; i < NC; ++i) {
            int col = ng * (N / 2) + lane + 32 * i;
            float* op = outT + col * STRIDE + outRow0 + rbase + 2 * r;
            float lo, hi;
            unpack2(acc[r][i], lo, hi);
            if (ADDTO) {
                float2 prev = *reinterpret_cast<const float2*>(op);
                lo += prev.x; hi += prev.y;
            } else {
                float b = bias[col];
                lo += b; hi += b;
            }
            if (RELU) { lo = fmaxf(lo, 0.0f); hi = fmaxf(hi, 0.0f); }
            *reinterpret_cast<float2*>(op) = make_float2(lo, hi);
        }
}

// ---------------------------------------------------------------------------
// Transposed LayerNorm: X[d][row] = LN(X + R)[d][row] over 192 dims, 32 rows.
// warp w: rows w*4 .. w*4+3; 8 lanes per row; lane dim set d = (lane&7) + 8j.
// ---------------------------------------------------------------------------
__device__ __forceinline__ void lnT(
    float* __restrict__ X, const float* __restrict__ R,
    const float* __restrict__ g, const float* __restrict__ be, int tid)
{
    const int lane = tid & 31, w = tid >> 5;
    const int row = w * 4 + (lane >> 3);
    const int ld  = lane & 7;
    float v[24];
    float s = 0.0f;
    #pragma unroll
    for (int j = 0; j < 24; ++j) {
        int d = ld + 8 * j;
        v[j] = X[d * STRIDE + row] + R[d * STRIDE + row];
        s += v[j];
    }
    s += __shfl_xor_sync(0xffffffffu, s, 1);
    s += __shfl_xor_sync(0xffffffffu, s, 2);
    s += __shfl_xor_sync(0xffffffffu, s, 4);
    float mean = s * (1.0f / 192.0f);
    float sq = 0.0f;
    #pragma unroll
    for (int j = 0; j < 24; ++j) { float dl = v[j] - mean; sq = fmaf(dl, dl, sq); }
    sq += __shfl_xor_sync(0xffffffffu, sq, 1);
    sq += __shfl_xor_sync(0xffffffffu, sq, 2);
    sq += __shfl_xor_sync(0xffffffffu, sq, 4);
    float rstd = rsqrtf(sq * (1.0f / 192.0f) + 1e-5f);
    #pragma unroll
    for (int j = 0; j < 24; ++j) {
        int d = ld + 8 * j;
        X[d * STRIDE + row] = (v[j] - mean) * rstd * __ldg(g + d) + __ldg(be + d);
    }
}

// ---------------------------------------------------------------------------
// Main fused kernel.
// smem: seqT [192][36] | A [192][36] | B [192][36]  (82944 bytes)
// token rows: t<16 = perc token of batch row t; t>=16 = tech token of row t-16
// ---------------------------------------------------------------------------
__global__ __launch_bounds__(NTHREADS, 2) void fusion_kernel(
    const float* __restrict__ perc, const float* __restrict__ tech,
    const float* __restrict__ bp,   const float* __restrict__ bt,
    const float* __restrict__ out_b,
    const float* __restrict__ ffn_b1, const float* __restrict__ ffn_b2,
    const float* __restrict__ ln1_g, const float* __restrict__ ln1_b,
    const float* __restrict__ ln2_g, const float* __restrict__ ln2_b,
    const float* __restrict__ cls_b1,
    const float* __restrict__ cls_w2, const float* __restrict__ cls_b2,
    const float* __restrict__ fp_b,
    float* __restrict__ out, int B)
{
    extern __shared__ float sm[];
    float* s_seq = sm;                       // [192][36]
    float* s_A   = sm + 192 * STRIDE;        // [192][36]
    float* s_B   = sm + 2 * 192 * STRIDE;    // [192][36]
    const float* gs = g_scratch;

    const int tid  = threadIdx.x;
    const int lane = tid & 31;
    const int b0   = blockIdx.x * ROWS_PER_BLOCK;

    // ---- load inputs transposed: perc -> A[d][r], tech -> B[d][r], r<16
    for (int idx = tid; idx < ROWS_PER_BLOCK * 48; idx += NTHREADS) {
        int r = idx / 48, q4 = idx % 48;
        int row = b0 + r; if (row >= B) row = B - 1;
        float4 pv = reinterpret_cast<const float4*>(perc + row * 192)[q4];
        float4 tv = reinterpret_cast<const float4*>(tech + row * 192)[q4];
        int d0 = 4 * q4;
        s_A[(d0 + 0) * STRIDE + r] = pv.x;
        s_A[(d0 + 1) * STRIDE + r] = pv.y;
        s_A[(d0 + 2) * STRIDE + r] = pv.z;
        s_A[(d0 + 3) * STRIDE + r] = pv.w;
        s_B[(d0 + 0) * STRIDE + r] = tv.x;
        s_B[(d0 + 1) * STRIDE + r] = tv.y;
        s_B[(d0 + 2) * STRIDE + r] = tv.z;
        s_B[(d0 + 3) * STRIDE + r] = tv.w;
    }
    __syncthreads();

    // ---- projections: perc tokens -> seqT rows 0..15, tech -> rows 16..31
    gemmT<16, 192, 192, false, false>(s_A, gs + OFF_WPT, 192, bp, s_seq, 0,  tid);
    gemmT<16, 192, 192, false, false>(s_B, gs + OFF_WTT, 192, bt, s_seq, 16, tid);
    __syncthreads();

    // ---- per-head: qkv -> A (q=dims 0..63, k=64..127, v=128..191); ctx -> B
    for (int h = 0; h < 3; ++h) {
        gemmT<32, 192, 192, false, false>(s_seq, gs + OFF_INWGT + h * 36864, 192,
                                          gs + OFF_INBG + h * 192, s_A, 0, tid);
        __syncthreads();
        if (tid < 128) {
            // lane decomposition: dq = bits[0:2), i = bit 2, pl = bits[3:5)
            int dq = tid & 3, i = (tid >> 2) & 1, pl = (tid >> 3) & 3;
            int p  = (tid >> 5) * 4 + pl;      // batch row / pair index
            int t0 = p, t1 = 16 + p;
            int ti = i ? t1 : t0;
            float s0 = 0.0f, s1 = 0.0f;
            #pragma unroll
            for (int j = 0; j < 16; ++j) {
                int d = dq + 4 * j;
                float qd = s_A[d * STRIDE + ti];
                float k0 = s_A[(64 + d) * STRIDE + t0];
                float k1 = s_A[(64 + d) * STRIDE + t1];
                s0 = fmaf(qd, k0, s0);
                s1 = fmaf(qd, k1, s1);
            }
            s0 += __shfl_xor_sync(0xffffffffu, s0, 1);
            s0 += __shfl_xor_sync(0xffffffffu, s0, 2);
            s1 += __shfl_xor_sync(0xffffffffu, s1, 1);
            s1 += __shfl_xor_sync(0xffffffffu, s1, 2);
            s0 *= 0.125f; s1 *= 0.125f;
            float m  = fmaxf(s0, s1);
            float e0 = __expf(s0 - m), e1 = __expf(s1 - m);
            float inv = 1.0f / (e0 + e1);
            float a0 = e0 * inv, a1 = e1 * inv;
            #pragma unroll
            for (int j = 0; j < 16; ++j) {
                int d = dq + 4 * j;
                float v0 = s_A[(128 + d) * STRIDE + t0];
                float v1 = s_A[(128 + d) * STRIDE + t1];
                s_B[(h * 64 + d) * STRIDE + ti] = a0 * v0 + a1 * v1;
            }
        }
        __syncthreads();
    }

    // ---- out-proj: ctx (B) -> attn_out (A)
    gemmT<32, 192, 192, false, false>(s_B, gs + OFF_OUTWT, 192, out_b, s_A, 0, tid);
    __syncthreads();

    // ---- LN1: seqT = LN(seqT + A)
    lnT(s_seq, s_A, ln1_g, ln1_b, tid);
    __syncthreads();

    // ---- FFN: two 192-hidden passes
    gemmT<32, 192, 192, true,  false>(s_seq, gs + OFF_FFN1T,       384, ffn_b1,       s_A, 0, tid);
    __syncthreads();
    gemmT<32, 192, 192, false, false>(s_A,   gs + OFF_FFN2T,       192, ffn_b2,       s_B, 0, tid);
    __syncthreads();
    gemmT<32, 192, 192, true,  false>(s_seq, gs + OFF_FFN1T + 192, 384, ffn_b1 + 192, s_A, 0, tid);
    __syncthreads();
    gemmT<32, 192, 192, false, true >(s_A,   gs + OFF_FFN2T + 192 * 192, 192, ffn_b2, s_B, 0, tid);
    __syncthreads();

    // ---- LN2: seqT = LN(seqT + B)
    lnT(s_seq, s_B, ln2_g, ln2_b, tid);
    __syncthreads();

    // ---- pool: A[d][r] = 0.5*(seqT[d][r] + seqT[d][16+r]), r<16
    for (int idx = tid; idx < 192 * 16; idx += NTHREADS) {
        int d = idx >> 4, r = idx & 15;
        s_A[d * STRIDE + r] = 0.5f * (s_seq[d * STRIDE + r] + s_seq[d * STRIDE + 16 + r]);
    }
    __syncthreads();

    // ---- heads: cls1(relu) -> B rows 0..15; fp -> B rows 16..31
    gemmT<16, 192, 192, true,  false>(s_A, gs + OFF_CLS1T, 192, cls_b1, s_B, 0,  tid);
    gemmT<16, 128, 192, false, false>(s_A, gs + OFF_FPT,   128, fp_b,   s_B, 16, tid);
    __syncthreads();

    // ---- cls2 + sigmoid: 16 rows x 3 logits
    if (tid < 48) {
        int r = tid & 15, j = tid >> 4;
        const float* w2 = cls_w2 + j * 192;
        float acc = 0.0f;
        #pragma unroll 8
        for (int c = 0; c < 192; ++c)
            acc = fmaf(s_B[c * STRIDE + r], __ldg(w2 + c), acc);
        acc += __ldg(cls_b2 + j);
        float prob = 1.0f / (1.0f + __expf(-acc));
        int row = b0 + r;
        if (row < B) out[j * B + row] = prob;
    }

    // ---- fp normalize + store: 16 lanes per row
    {
        int r = tid >> 4, cl = tid & 15;
        float f[8];
        float ss = 0.0f;
        #pragma unroll
        for (int j = 0; j < 8; ++j) {
            int c = cl + 16 * j;
            f[j] = s_B[c * STRIDE + 16 + r];
            ss = fmaf(f[j], f[j], ss);
        }
        ss += __shfl_xor_sync(0xffffffffu, ss, 1);
        ss += __shfl_xor_sync(0xffffffffu, ss, 2);
        ss += __shfl_xor_sync(0xffffffffu, ss, 4);
        ss += __shfl_xor_sync(0xffffffffu, ss, 8);
        float inv = 1.0f / fmaxf(sqrtf(ss), 1e-12f);
        int row = b0 + r;
        if (row < B) {
            float* o = out + 3 * B + row * 128;
            #pragma unroll
            for (int j = 0; j < 8; ++j) o[cl + 16 * j] = f[j] * inv;
        }
    }
}

// ---------------------------------------------------------------------------
// Launch
// ---------------------------------------------------------------------------
extern "C" void kernel_launch(void* const* d_in, const int* in_sizes, int n_in,
                              void* d_out, int out_size) {
    const float* perc   = (const float*)d_in[0];
    const float* tech   = (const float*)d_in[1];
    const float* Wp     = (const float*)d_in[2];
    const float* bp     = (const float*)d_in[3];
    const float* Wt     = (const float*)d_in[4];
    const float* bt     = (const float*)d_in[5];
    const float* in_w   = (const float*)d_in[6];
    const float* in_b   = (const float*)d_in[7];
    const float* out_w  = (const float*)d_in[8];
    const float* out_b  = (const float*)d_in[9];
    const float* ffn_w1 = (const float*)d_in[10];
    const float* ffn_b1 = (const float*)d_in[11];
    const float* ffn_w2 = (const float*)d_in[12];
    const float* ffn_b2 = (const float*)d_in[13];
    const float* ln1_g  = (const float*)d_in[14];
    const float* ln1_b  = (const float*)d_in[15];
    const float* ln2_g  = (const float*)d_in[16];
    const float* ln2_b  = (const float*)d_in[17];
    const float* cls_w1 = (const float*)d_in[18];
    const float* cls_b1 = (const float*)d_in[19];
    const float* cls_w2 = (const float*)d_in[20];
    const float* cls_b2 = (const float*)d_in[21];
    const float* fp_w   = (const float*)d_in[22];
    const float* fp_b   = (const float*)d_in[23];
    float* outp = (float*)d_out;

    const int B = in_sizes[0] / D_MODEL;

    // merged weight prep (runs inside the graph each replay)
    k_prep<<<296, 256>>>(Wp, Wt, out_w, ffn_w1, ffn_w2, cls_w1, fp_w, in_w, in_b);

    const int smemBytes = 3 * 192 * STRIDE * (int)sizeof(float); // 82944
    cudaFuncSetAttribute(fusion_kernel, cudaFuncAttributeMaxDynamicSharedMemorySize, smemBytes);

    int grid = (B + ROWS_PER_BLOCK - 1) / ROWS_PER_BLOCK;
    fusion_kernel<<<grid, NTHREADS, smemBytes>>>(
        perc, tech, bp, bt, out_b, ffn_b1, ffn_b2,
        ln1_g, ln1_b, ln2_g, ln2_b, cls_b1, cls_w2, cls_b2, fp_b,
        outp, B);
}